// round 16
// baseline (speedup 1.0000x reference)
#include <cuda_runtime.h>
#include <cuda_fp16.h>
#include <math.h>
#include <cstdint>

// Problem: inputs (4, 8, 24, 24, 64) fp32 -> B=4, N=4608, C=64
// out = gamma * softmax(Q Q^T) Q + inputs,  Q = K = V = inputs.reshape(B,N,C)
//
// Flash attention, mma.sync.m16n8k16 (R12 structure byte-for-byte, except
// softmax moved to the exp2 domain):
//   S  = Q K^T : fp16x3 (qh*kh + qh*kl + ql*kh), Q pre-scaled by log2(e)
//   O += P V   : fp16x1 (ph*vh)
// Warp tiling M=32 x N=64 (8 warps = 4 row-quarters x 2 k-halves), split-K
// combine at end; KV double-buffered via per-tile LDG prefetch + cvt_store
// (R12 schedule); one __syncthreads per tile; exp = bare ex2.approx.

#define BATCH   4
#define NTOK    4608
#define CDIM    64
#define BM      128
#define BN      128
#define NTILES  (NTOK / BN)   // 36

#define LDH 72                // half-tile row stride (64 + 8 pad)

#define QH_B    0
#define QL_B    18432
#define KB_H(buf) (36864 + (buf) * 36864)
#define KB_L(buf) (KB_H(buf) + 18432)
#define SMEM_DYN  (36864 + 2 * 36864)   // 110592

// epilogue aliases (Q tiles / KV buffer 0 dead by then)
#define OEP_LD  66
#define ML_B    36864

#define LOG2E 1.44269504088896340736f

// ---------------- PTX helpers ----------------
__device__ __forceinline__ uint32_t smem_u32(const void* p) {
    uint32_t a;
    asm("{ .reg .u64 t; cvta.to.shared.u64 t, %1; cvt.u32.u64 %0, t; }" : "=r"(a) : "l"(p));
    return a;
}

__device__ __forceinline__ float ex2(float x) {   // 2^x, single MUFU op
    float y;
    asm("ex2.approx.ftz.f32 %0, %1;" : "=f"(y) : "f"(x));
    return y;
}

#define LDSM_X4(r0, r1, r2, r3, a) \
    asm volatile("ldmatrix.sync.aligned.m8n8.x4.shared.b16 {%0,%1,%2,%3}, [%4];" \
        : "=r"(r0), "=r"(r1), "=r"(r2), "=r"(r3) : "r"(a))
#define LDSM_X4T(r0, r1, r2, r3, a) \
    asm volatile("ldmatrix.sync.aligned.m8n8.x4.trans.shared.b16 {%0,%1,%2,%3}, [%4];" \
        : "=r"(r0), "=r"(r1), "=r"(r2), "=r"(r3) : "r"(a))

#define MMA16816(c, a0, a1, a2, a3, b0, b1) \
    asm volatile("mma.sync.aligned.m16n8k16.row.col.f32.f16.f16.f32 " \
        "{%0,%1,%2,%3}, {%4,%5,%6,%7}, {%8,%9}, {%0,%1,%2,%3};" \
        : "+f"((c)[0]), "+f"((c)[1]), "+f"((c)[2]), "+f"((c)[3]) \
        : "r"(a0), "r"(a1), "r"(a2), "r"(a3), "r"(b0), "r"(b1))

__device__ __forceinline__ uint32_t h2u(half2 h) { return *(uint32_t*)&h; }

__device__ __forceinline__ void cvt_store(char* sm_h, char* sm_l, int r, int c, float4 v) {
    half2 h01 = __floats2half2_rn(v.x, v.y);
    half2 h23 = __floats2half2_rn(v.z, v.w);
    half2 l01 = __floats2half2_rn(v.x - __low2float(h01), v.y - __high2float(h01));
    half2 l23 = __floats2half2_rn(v.z - __low2float(h23), v.w - __high2float(h23));
    *(half2*)(sm_h + (r * LDH + c) * 2)     = h01;
    *(half2*)(sm_h + (r * LDH + c + 2) * 2) = h23;
    *(half2*)(sm_l + (r * LDH + c) * 2)     = l01;
    *(half2*)(sm_l + (r * LDH + c + 2) * 2) = l23;
}

// ---------------- fused attention ----------------
__global__ __launch_bounds__(256, 1)
void attn_mma_pv1x_kernel(const float* __restrict__ x,
                          const float* __restrict__ gamma_p,
                          float* __restrict__ out)
{
    extern __shared__ char sm[];
    const uint32_t smb = smem_u32(sm);

    const int tid  = threadIdx.x;
    const int w    = tid >> 5;
    const int lane = tid & 31;
    const int g    = lane >> 2;
    const int t4   = lane & 3;
    const int wm   = w & 3;        // row quarter: rows 32*wm .. +31
    const int wk   = w >> 2;       // k-half: S cols / V rows 64*wk .. +63

    const int b    = blockIdx.y;
    const int row0 = blockIdx.x * BM;
    const float* xb = x + (size_t)b * NTOK * CDIM;

    const int rload = tid >> 1;
    const int hload = (tid & 1) << 5;

    // ---- preamble: load Q tile (scaled by log2e) + KV tile 0 (hi/lo split)
    {
        const float4* qsrc = (const float4*)(xb + (size_t)(row0 + rload) * CDIM + hload);
        const float4* ksrc = (const float4*)(xb + (size_t)rload * CDIM + hload);
        #pragma unroll
        for (int i = 0; i < 8; i++) {
            float4 qv = qsrc[i];
            qv.x *= LOG2E; qv.y *= LOG2E; qv.z *= LOG2E; qv.w *= LOG2E;
            cvt_store(sm + QH_B, sm + QL_B, rload, hload + i * 4, qv);
            cvt_store(sm + KB_H(0), sm + KB_L(0), rload, hload + i * 4, ksrc[i]);
        }
    }
    __syncthreads();

    // per-warp online softmax state (exp2 domain)
    float m[4], l[4];
    #pragma unroll
    for (int i = 0; i < 4; i++) { m[i] = -INFINITY; l[i] = 0.f; }
    float o[2][8][4];
    #pragma unroll
    for (int mt = 0; mt < 2; mt++)
        #pragma unroll
        for (int nt = 0; nt < 8; nt++)
            #pragma unroll
            for (int j = 0; j < 4; j++) o[mt][nt][j] = 0.f;

    const int l15 = lane & 15;
    const uint32_t kfrag_base = (uint32_t)((l15 & 7) * LDH + (l15 >> 3) * 8
                                           + (lane >> 4) * 8 * LDH) * 2;
    const uint32_t vfrag_base = (uint32_t)(l15 * LDH) * 2 + (uint32_t)(lane >> 4) * 16;
    const uint32_t qrow = (uint32_t)(wm * 32 + l15);
    const uint32_t qcol = (uint32_t)((lane >> 4) * 8);

    for (int t = 0; t < NTILES; t++) {
        const int cur = t & 1, nxt = cur ^ 1;
        const uint32_t kh = smb + KB_H(cur);
        const uint32_t kl = smb + KB_L(cur);

        // ---- prefetch next KV tile (GMEM/L2 -> regs)
        float4 pre[8];
        if (t + 1 < NTILES) {
            const float4* src = (const float4*)(xb + (size_t)((t + 1) * BN + rload) * CDIM + hload);
            #pragma unroll
            for (int i = 0; i < 8; i++) pre[i] = src[i];
        }

        // ---- S = Q K^T over this warp's 64 cols (fp16x3)
        float c[2][8][4];
        #pragma unroll
        for (int mt = 0; mt < 2; mt++)
            #pragma unroll
            for (int nt = 0; nt < 8; nt++) {
                c[mt][nt][0] = 0.f; c[mt][nt][1] = 0.f;
                c[mt][nt][2] = 0.f; c[mt][nt][3] = 0.f;
            }

        #pragma unroll
        for (int kb = 0; kb < 4; kb++) {
            uint32_t q0h[4], q1h[4], q0l[4], q1l[4];
            {
                uint32_t qo0 = (uint32_t)(qrow * LDH + kb * 16) * 2 + qcol * 2;
                uint32_t qo1 = qo0 + (uint32_t)(16 * LDH) * 2;
                LDSM_X4(q0h[0], q0h[1], q0h[2], q0h[3], smb + QH_B + qo0);
                LDSM_X4(q1h[0], q1h[1], q1h[2], q1h[3], smb + QH_B + qo1);
                LDSM_X4(q0l[0], q0l[1], q0l[2], q0l[3], smb + QL_B + qo0);
                LDSM_X4(q1l[0], q1l[1], q1l[2], q1l[3], smb + QL_B + qo1);
            }
            #pragma unroll
            for (int np = 0; np < 4; np++) {
                uint32_t off = (uint32_t)((wk * 64 + np * 16) * LDH + kb * 16) * 2 + kfrag_base;
                uint32_t bh0, bh1, bh2, bh3, bl0, bl1, bl2, bl3;
                LDSM_X4(bh0, bh1, bh2, bh3, kh + off);
                LDSM_X4(bl0, bl1, bl2, bl3, kl + off);
                MMA16816(c[0][2*np],   q0h[0], q0h[1], q0h[2], q0h[3], bh0, bh1);
                MMA16816(c[0][2*np+1], q0h[0], q0h[1], q0h[2], q0h[3], bh2, bh3);
                MMA16816(c[1][2*np],   q1h[0], q1h[1], q1h[2], q1h[3], bh0, bh1);
                MMA16816(c[1][2*np+1], q1h[0], q1h[1], q1h[2], q1h[3], bh2, bh3);
                MMA16816(c[0][2*np],   q0h[0], q0h[1], q0h[2], q0h[3], bl0, bl1);
                MMA16816(c[0][2*np+1], q0h[0], q0h[1], q0h[2], q0h[3], bl2, bl3);
                MMA16816(c[1][2*np],   q1h[0], q1h[1], q1h[2], q1h[3], bl0, bl1);
                MMA16816(c[1][2*np+1], q1h[0], q1h[1], q1h[2], q1h[3], bl2, bl3);
                MMA16816(c[0][2*np],   q0l[0], q0l[1], q0l[2], q0l[3], bh0, bh1);
                MMA16816(c[0][2*np+1], q0l[0], q0l[1], q0l[2], q0l[3], bh2, bh3);
                MMA16816(c[1][2*np],   q1l[0], q1l[1], q1l[2], q1l[3], bh0, bh1);
                MMA16816(c[1][2*np+1], q1l[0], q1l[1], q1l[2], q1l[3], bh2, bh3);
            }
        }

        // ---- store prefetched tile to the other buffer
        if (t + 1 < NTILES) {
            #pragma unroll
            for (int i = 0; i < 8; i++)
                cvt_store(sm + KB_H(nxt), sm + KB_L(nxt), rload, hload + i * 4, pre[i]);
        }

        // ---- warp-local online softmax over this warp's 64 cols (exp2 domain)
        float tm[4];
        #pragma unroll
        for (int i = 0; i < 4; i++) tm[i] = -INFINITY;
        #pragma unroll
        for (int mt = 0; mt < 2; mt++)
            #pragma unroll
            for (int nt = 0; nt < 8; nt++) {
                tm[2*mt]   = fmaxf(tm[2*mt],   fmaxf(c[mt][nt][0], c[mt][nt][1]));
                tm[2*mt+1] = fmaxf(tm[2*mt+1], fmaxf(c[mt][nt][2], c[mt][nt][3]));
            }
        #pragma unroll
        for (int off = 1; off < 4; off <<= 1)
            #pragma unroll
            for (int i = 0; i < 4; i++)
                tm[i] = fmaxf(tm[i], __shfl_xor_sync(0xffffffffu, tm[i], off));

        float nm[4], sc[4];
        #pragma unroll
        for (int i = 0; i < 4; i++) {
            nm[i] = fmaxf(m[i], tm[i]);
            sc[i] = ex2(m[i] - nm[i]);   // 0 on first tile
            m[i]  = nm[i];
            l[i] *= sc[i];
        }
        #pragma unroll
        for (int mt = 0; mt < 2; mt++)
            #pragma unroll
            for (int nt = 0; nt < 8; nt++) {
                o[mt][nt][0] *= sc[2*mt];   o[mt][nt][1] *= sc[2*mt];
                o[mt][nt][2] *= sc[2*mt+1]; o[mt][nt][3] *= sc[2*mt+1];
            }

        // ---- PV over this warp's k-half, per 16-wide k-chunk (fp16x1)
        #pragma unroll
        for (int kc = 0; kc < 4; kc++) {
            uint32_t pah[2][4];
            #pragma unroll
            for (int mt = 0; mt < 2; mt++) {
                const float* cA = c[mt][2*kc];
                const float* cB = c[mt][2*kc+1];
                float eA0 = ex2(cA[0] - nm[2*mt]);
                float eA1 = ex2(cA[1] - nm[2*mt]);
                float eA2 = ex2(cA[2] - nm[2*mt+1]);
                float eA3 = ex2(cA[3] - nm[2*mt+1]);
                float eB0 = ex2(cB[0] - nm[2*mt]);
                float eB1 = ex2(cB[1] - nm[2*mt]);
                float eB2 = ex2(cB[2] - nm[2*mt+1]);
                float eB3 = ex2(cB[3] - nm[2*mt+1]);
                l[2*mt]   += eA0 + eA1 + eB0 + eB1;
                l[2*mt+1] += eA2 + eA3 + eB2 + eB3;
                pah[mt][0] = h2u(__floats2half2_rn(eA0, eA1));
                pah[mt][1] = h2u(__floats2half2_rn(eA2, eA3));
                pah[mt][2] = h2u(__floats2half2_rn(eB0, eB1));
                pah[mt][3] = h2u(__floats2half2_rn(eB2, eB3));
            }

            const uint32_t voffb = (uint32_t)((wk * 64 + kc * 16) * LDH) * 2 + vfrag_base;
            #pragma unroll
            for (int np = 0; np < 4; np++) {
                uint32_t v0, v1, v2, v3;
                LDSM_X4T(v0, v1, v2, v3, kh + voffb + (uint32_t)np * 32);
                MMA16816(o[0][2*np],   pah[0][0], pah[0][1], pah[0][2], pah[0][3], v0, v1);
                MMA16816(o[0][2*np+1], pah[0][0], pah[0][1], pah[0][2], pah[0][3], v2, v3);
                MMA16816(o[1][2*np],   pah[1][0], pah[1][1], pah[1][2], pah[1][3], v0, v1);
                MMA16816(o[1][2*np+1], pah[1][0], pah[1][1], pah[1][2], pah[1][3], v2, v3);
            }
        }

        __syncthreads();
    }

    // ---- reduce l over the 4 lanes of each row group (warp-local)
    #pragma unroll
    for (int off = 1; off < 4; off <<= 1)
        #pragma unroll
        for (int i = 0; i < 4; i++)
            l[i] += __shfl_xor_sync(0xffffffffu, l[i], off);

    // ---- split-K combine through SMEM: k-half 1 publishes, k-half 0 merges
    float* smO = (float*)sm;               // [128][OEP_LD] fp32 partial O
    float* smM = (float*)(sm + ML_B);      // [128] partial m
    float* smL = smM + 128;                // [128] partial l

    if (wk == 1) {
        #pragma unroll
        for (int mt = 0; mt < 2; mt++) {
            const int r = wm * 32 + mt * 16 + g;
            if (t4 == 0) {
                smM[r]     = m[2*mt];   smL[r]     = l[2*mt];
                smM[r + 8] = m[2*mt+1]; smL[r + 8] = l[2*mt+1];
            }
            #pragma unroll
            for (int nt = 0; nt < 8; nt++) {
                const int col = nt * 8 + t4 * 2;
                smO[r * OEP_LD + col]           = o[mt][nt][0];
                smO[r * OEP_LD + col + 1]       = o[mt][nt][1];
                smO[(r + 8) * OEP_LD + col]     = o[mt][nt][2];
                smO[(r + 8) * OEP_LD + col + 1] = o[mt][nt][3];
            }
        }
    }
    __syncthreads();

    if (wk == 0) {
        const float gm = *gamma_p;
        #pragma unroll
        for (int mt = 0; mt < 2; mt++) {
            #pragma unroll
            for (int hh = 0; hh < 2; hh++) {
                const int rl = wm * 32 + mt * 16 + g + 8 * hh;
                const float mp = smM[rl], lp = smL[rl];
                const float mm = fmaxf(m[2*mt+hh], mp);
                const float s  = ex2(m[2*mt+hh] - mm);
                const float sp = ex2(mp - mm);
                const float inv = 1.f / (l[2*mt+hh] * s + lp * sp);
                const int rg = row0 + rl;
                #pragma unroll
                for (int nt = 0; nt < 8; nt++) {
                    const int col = nt * 8 + t4 * 2;
                    float v0 = o[mt][nt][2*hh]     * s + smO[rl * OEP_LD + col]     * sp;
                    float v1 = o[mt][nt][2*hh + 1] * s + smO[rl * OEP_LD + col + 1] * sp;
                    float2 xi = *(const float2*)(xb + (size_t)rg * CDIM + col);
                    float2 res;
                    res.x = fmaf(gm, v0 * inv, xi.x);
                    res.y = fmaf(gm, v1 * inv, xi.y);
                    *(float2*)(out + ((size_t)b * NTOK + rg) * CDIM + col) = res;
                }
            }
        }
    }
}

extern "C" void kernel_launch(void* const* d_in, const int* in_sizes, int n_in,
                              void* d_out, int out_size)
{
    const float* x     = (const float*)d_in[0];
    const float* gamma = (const float*)d_in[1];
    float* out = (float*)d_out;

    cudaFuncSetAttribute(attn_mma_pv1x_kernel,
                         cudaFuncAttributeMaxDynamicSharedMemorySize, SMEM_DYN);

    dim3 grid(NTOK / BM, BATCH);   // (36, 4) = 144 CTAs ~ one wave
    attn_mma_pv1x_kernel<<<grid, 256, SMEM_DYN>>>(x, gamma, out);
}

// round 17
// speedup vs baseline: 1.1148x; 1.1148x over previous
#include <cuda_runtime.h>
#include <cuda_fp16.h>
#include <math.h>
#include <cstdint>

// Problem: inputs (4, 8, 24, 24, 64) fp32 -> B=4, N=4608, C=64
// out = gamma * softmax(Q Q^T) Q + inputs,  Q = K = V = inputs.reshape(B,N,C)
//
// Flash attention, mma.sync.m16n8k16 (converged R12 configuration):
//   S  = Q K^T : fp16x3 (qh*kh + qh*kl + ql*kh)
//   O += P V   : fp16x1 (ph*vh)
// Warp tiling M=32 x N=64: 8 warps = 4 row-quarters x 2 k-halves; split-K
// combine at end; KV double-buffered (LDG prefetch -> cvt -> STS absorbed
// into MMA slack); one __syncthreads per tile.

#define BATCH   4
#define NTOK    4608
#define CDIM    64
#define BM      128
#define BN      128
#define NTILES  (NTOK / BN)   // 36

#define LDH 72                // half-tile row stride (64 + 8 pad)

#define QH_B    0
#define QL_B    18432
#define KB_H(buf) (36864 + (buf) * 36864)
#define KB_L(buf) (KB_H(buf) + 18432)
#define SMEM_DYN  (36864 + 2 * 36864)   // 110592

// epilogue aliases (Q tiles / KV buffer 0 dead by then)
#define OEP_LD  66
#define ML_B    36864

// ---------------- PTX helpers ----------------
__device__ __forceinline__ uint32_t smem_u32(const void* p) {
    uint32_t a;
    asm("{ .reg .u64 t; cvta.to.shared.u64 t, %1; cvt.u32.u64 %0, t; }" : "=r"(a) : "l"(p));
    return a;
}

#define LDSM_X4(r0, r1, r2, r3, a) \
    asm volatile("ldmatrix.sync.aligned.m8n8.x4.shared.b16 {%0,%1,%2,%3}, [%4];" \
        : "=r"(r0), "=r"(r1), "=r"(r2), "=r"(r3) : "r"(a))
#define LDSM_X4T(r0, r1, r2, r3, a) \
    asm volatile("ldmatrix.sync.aligned.m8n8.x4.trans.shared.b16 {%0,%1,%2,%3}, [%4];" \
        : "=r"(r0), "=r"(r1), "=r"(r2), "=r"(r3) : "r"(a))

#define MMA16816(c, a0, a1, a2, a3, b0, b1) \
    asm volatile("mma.sync.aligned.m16n8k16.row.col.f32.f16.f16.f32 " \
        "{%0,%1,%2,%3}, {%4,%5,%6,%7}, {%8,%9}, {%0,%1,%2,%3};" \
        : "+f"((c)[0]), "+f"((c)[1]), "+f"((c)[2]), "+f"((c)[3]) \
        : "r"(a0), "r"(a1), "r"(a2), "r"(a3), "r"(b0), "r"(b1))

__device__ __forceinline__ uint32_t h2u(half2 h) { return *(uint32_t*)&h; }

__device__ __forceinline__ void cvt_store(char* sm_h, char* sm_l, int r, int c, float4 v) {
    half2 h01 = __floats2half2_rn(v.x, v.y);
    half2 h23 = __floats2half2_rn(v.z, v.w);
    half2 l01 = __floats2half2_rn(v.x - __low2float(h01), v.y - __high2float(h01));
    half2 l23 = __floats2half2_rn(v.z - __low2float(h23), v.w - __high2float(h23));
    *(half2*)(sm_h + (r * LDH + c) * 2)     = h01;
    *(half2*)(sm_h + (r * LDH + c + 2) * 2) = h23;
    *(half2*)(sm_l + (r * LDH + c) * 2)     = l01;
    *(half2*)(sm_l + (r * LDH + c + 2) * 2) = l23;
}

// ---------------- fused attention ----------------
__global__ __launch_bounds__(256, 1)
void attn_mma_pv1_kernel(const float* __restrict__ x,
                         const float* __restrict__ gamma_p,
                         float* __restrict__ out)
{
    extern __shared__ char sm[];
    const uint32_t smb = smem_u32(sm);

    const int tid  = threadIdx.x;
    const int w    = tid >> 5;
    const int lane = tid & 31;
    const int g    = lane >> 2;
    const int t4   = lane & 3;
    const int wm   = w & 3;        // row quarter: rows 32*wm .. +31
    const int wk   = w >> 2;       // k-half: S cols / V rows 64*wk .. +63

    const int b    = blockIdx.y;
    const int row0 = blockIdx.x * BM;
    const float* xb = x + (size_t)b * NTOK * CDIM;

    const int rload = tid >> 1;
    const int hload = (tid & 1) << 5;

    // ---- preamble: load Q tile + KV tile 0 (hi/lo split)
    {
        const float4* qsrc = (const float4*)(xb + (size_t)(row0 + rload) * CDIM + hload);
        const float4* ksrc = (const float4*)(xb + (size_t)rload * CDIM + hload);
        #pragma unroll
        for (int i = 0; i < 8; i++) {
            cvt_store(sm + QH_B, sm + QL_B, rload, hload + i * 4, qsrc[i]);
            cvt_store(sm + KB_H(0), sm + KB_L(0), rload, hload + i * 4, ksrc[i]);
        }
    }
    __syncthreads();

    // per-warp online softmax state
    float m[4], l[4];
    #pragma unroll
    for (int i = 0; i < 4; i++) { m[i] = -INFINITY; l[i] = 0.f; }
    float o[2][8][4];
    #pragma unroll
    for (int mt = 0; mt < 2; mt++)
        #pragma unroll
        for (int nt = 0; nt < 8; nt++)
            #pragma unroll
            for (int j = 0; j < 4; j++) o[mt][nt][j] = 0.f;

    const int l15 = lane & 15;
    const uint32_t kfrag_base = (uint32_t)((l15 & 7) * LDH + (l15 >> 3) * 8
                                           + (lane >> 4) * 8 * LDH) * 2;
    const uint32_t vfrag_base = (uint32_t)(l15 * LDH) * 2 + (uint32_t)(lane >> 4) * 16;
    const uint32_t qrow = (uint32_t)(wm * 32 + l15);
    const uint32_t qcol = (uint32_t)((lane >> 4) * 8);

    for (int t = 0; t < NTILES; t++) {
        const int cur = t & 1, nxt = cur ^ 1;
        const uint32_t kh = smb + KB_H(cur);
        const uint32_t kl = smb + KB_L(cur);

        // ---- prefetch next KV tile (GMEM/L2 -> regs)
        float4 pre[8];
        if (t + 1 < NTILES) {
            const float4* src = (const float4*)(xb + (size_t)((t + 1) * BN + rload) * CDIM + hload);
            #pragma unroll
            for (int i = 0; i < 8; i++) pre[i] = src[i];
        }

        // ---- S = Q K^T over this warp's 64 cols (fp16x3)
        float c[2][8][4];
        #pragma unroll
        for (int mt = 0; mt < 2; mt++)
            #pragma unroll
            for (int nt = 0; nt < 8; nt++) {
                c[mt][nt][0] = 0.f; c[mt][nt][1] = 0.f;
                c[mt][nt][2] = 0.f; c[mt][nt][3] = 0.f;
            }

        #pragma unroll
        for (int kb = 0; kb < 4; kb++) {
            uint32_t q0h[4], q1h[4], q0l[4], q1l[4];
            {
                uint32_t qo0 = (uint32_t)(qrow * LDH + kb * 16) * 2 + qcol * 2;
                uint32_t qo1 = qo0 + (uint32_t)(16 * LDH) * 2;
                LDSM_X4(q0h[0], q0h[1], q0h[2], q0h[3], smb + QH_B + qo0);
                LDSM_X4(q1h[0], q1h[1], q1h[2], q1h[3], smb + QH_B + qo1);
                LDSM_X4(q0l[0], q0l[1], q0l[2], q0l[3], smb + QL_B + qo0);
                LDSM_X4(q1l[0], q1l[1], q1l[2], q1l[3], smb + QL_B + qo1);
            }
            #pragma unroll
            for (int np = 0; np < 4; np++) {
                uint32_t off = (uint32_t)((wk * 64 + np * 16) * LDH + kb * 16) * 2 + kfrag_base;
                uint32_t bh0, bh1, bh2, bh3, bl0, bl1, bl2, bl3;
                LDSM_X4(bh0, bh1, bh2, bh3, kh + off);
                LDSM_X4(bl0, bl1, bl2, bl3, kl + off);
                MMA16816(c[0][2*np],   q0h[0], q0h[1], q0h[2], q0h[3], bh0, bh1);
                MMA16816(c[0][2*np+1], q0h[0], q0h[1], q0h[2], q0h[3], bh2, bh3);
                MMA16816(c[1][2*np],   q1h[0], q1h[1], q1h[2], q1h[3], bh0, bh1);
                MMA16816(c[1][2*np+1], q1h[0], q1h[1], q1h[2], q1h[3], bh2, bh3);
                MMA16816(c[0][2*np],   q0h[0], q0h[1], q0h[2], q0h[3], bl0, bl1);
                MMA16816(c[0][2*np+1], q0h[0], q0h[1], q0h[2], q0h[3], bl2, bl3);
                MMA16816(c[1][2*np],   q1h[0], q1h[1], q1h[2], q1h[3], bl0, bl1);
                MMA16816(c[1][2*np+1], q1h[0], q1h[1], q1h[2], q1h[3], bl2, bl3);
                MMA16816(c[0][2*np],   q0l[0], q0l[1], q0l[2], q0l[3], bh0, bh1);
                MMA16816(c[0][2*np+1], q0l[0], q0l[1], q0l[2], q0l[3], bh2, bh3);
                MMA16816(c[1][2*np],   q1l[0], q1l[1], q1l[2], q1l[3], bh0, bh1);
                MMA16816(c[1][2*np+1], q1l[0], q1l[1], q1l[2], q1l[3], bh2, bh3);
            }
        }

        // ---- store prefetched tile to the other buffer
        if (t + 1 < NTILES) {
            #pragma unroll
            for (int i = 0; i < 8; i++)
                cvt_store(sm + KB_H(nxt), sm + KB_L(nxt), rload, hload + i * 4, pre[i]);
        }

        // ---- warp-local online softmax over this warp's 64 cols
        float tm[4];
        #pragma unroll
        for (int i = 0; i < 4; i++) tm[i] = -INFINITY;
        #pragma unroll
        for (int mt = 0; mt < 2; mt++)
            #pragma unroll
            for (int nt = 0; nt < 8; nt++) {
                tm[2*mt]   = fmaxf(tm[2*mt],   fmaxf(c[mt][nt][0], c[mt][nt][1]));
                tm[2*mt+1] = fmaxf(tm[2*mt+1], fmaxf(c[mt][nt][2], c[mt][nt][3]));
            }
        #pragma unroll
        for (int off = 1; off < 4; off <<= 1)
            #pragma unroll
            for (int i = 0; i < 4; i++)
                tm[i] = fmaxf(tm[i], __shfl_xor_sync(0xffffffffu, tm[i], off));

        float nm[4], sc[4];
        #pragma unroll
        for (int i = 0; i < 4; i++) {
            nm[i] = fmaxf(m[i], tm[i]);
            sc[i] = __expf(m[i] - nm[i]);
            m[i]  = nm[i];
            l[i] *= sc[i];
        }
        #pragma unroll
        for (int mt = 0; mt < 2; mt++)
            #pragma unroll
            for (int nt = 0; nt < 8; nt++) {
                o[mt][nt][0] *= sc[2*mt];   o[mt][nt][1] *= sc[2*mt];
                o[mt][nt][2] *= sc[2*mt+1]; o[mt][nt][3] *= sc[2*mt+1];
            }

        // ---- PV over this warp's k-half, per 16-wide k-chunk (fp16x1)
        #pragma unroll
        for (int kc = 0; kc < 4; kc++) {
            uint32_t pah[2][4];
            #pragma unroll
            for (int mt = 0; mt < 2; mt++) {
                const float* cA = c[mt][2*kc];
                const float* cB = c[mt][2*kc+1];
                float eA0 = __expf(cA[0] - nm[2*mt]);
                float eA1 = __expf(cA[1] - nm[2*mt]);
                float eA2 = __expf(cA[2] - nm[2*mt+1]);
                float eA3 = __expf(cA[3] - nm[2*mt+1]);
                float eB0 = __expf(cB[0] - nm[2*mt]);
                float eB1 = __expf(cB[1] - nm[2*mt]);
                float eB2 = __expf(cB[2] - nm[2*mt+1]);
                float eB3 = __expf(cB[3] - nm[2*mt+1]);
                l[2*mt]   += eA0 + eA1 + eB0 + eB1;
                l[2*mt+1] += eA2 + eA3 + eB2 + eB3;
                pah[mt][0] = h2u(__floats2half2_rn(eA0, eA1));
                pah[mt][1] = h2u(__floats2half2_rn(eA2, eA3));
                pah[mt][2] = h2u(__floats2half2_rn(eB0, eB1));
                pah[mt][3] = h2u(__floats2half2_rn(eB2, eB3));
            }

            const uint32_t voffb = (uint32_t)((wk * 64 + kc * 16) * LDH) * 2 + vfrag_base;
            #pragma unroll
            for (int np = 0; np < 4; np++) {
                uint32_t v0, v1, v2, v3;
                LDSM_X4T(v0, v1, v2, v3, kh + voffb + (uint32_t)np * 32);
                MMA16816(o[0][2*np],   pah[0][0], pah[0][1], pah[0][2], pah[0][3], v0, v1);
                MMA16816(o[0][2*np+1], pah[0][0], pah[0][1], pah[0][2], pah[0][3], v2, v3);
                MMA16816(o[1][2*np],   pah[1][0], pah[1][1], pah[1][2], pah[1][3], v0, v1);
                MMA16816(o[1][2*np+1], pah[1][0], pah[1][1], pah[1][2], pah[1][3], v2, v3);
            }
        }

        __syncthreads();
    }

    // ---- reduce l over the 4 lanes of each row group (warp-local)
    #pragma unroll
    for (int off = 1; off < 4; off <<= 1)
        #pragma unroll
        for (int i = 0; i < 4; i++)
            l[i] += __shfl_xor_sync(0xffffffffu, l[i], off);

    // ---- split-K combine through SMEM: k-half 1 publishes, k-half 0 merges
    float* smO = (float*)sm;               // [128][OEP_LD] fp32 partial O
    float* smM = (float*)(sm + ML_B);      // [128] partial m
    float* smL = smM + 128;                // [128] partial l

    if (wk == 1) {
        #pragma unroll
        for (int mt = 0; mt < 2; mt++) {
            const int r = wm * 32 + mt * 16 + g;
            if (t4 == 0) {
                smM[r]     = m[2*mt];   smL[r]     = l[2*mt];
                smM[r + 8] = m[2*mt+1]; smL[r + 8] = l[2*mt+1];
            }
            #pragma unroll
            for (int nt = 0; nt < 8; nt++) {
                const int col = nt * 8 + t4 * 2;
                smO[r * OEP_LD + col]           = o[mt][nt][0];
                smO[r * OEP_LD + col + 1]       = o[mt][nt][1];
                smO[(r + 8) * OEP_LD + col]     = o[mt][nt][2];
                smO[(r + 8) * OEP_LD + col + 1] = o[mt][nt][3];
            }
        }
    }
    __syncthreads();

    if (wk == 0) {
        const float gm = *gamma_p;
        #pragma unroll
        for (int mt = 0; mt < 2; mt++) {
            #pragma unroll
            for (int hh = 0; hh < 2; hh++) {
                const int rl = wm * 32 + mt * 16 + g + 8 * hh;
                const float mp = smM[rl], lp = smL[rl];
                const float mm = fmaxf(m[2*mt+hh], mp);
                const float s  = __expf(m[2*mt+hh] - mm);
                const float sp = __expf(mp - mm);
                const float inv = 1.f / (l[2*mt+hh] * s + lp * sp);
                const int rg = row0 + rl;
                #pragma unroll
                for (int nt = 0; nt < 8; nt++) {
                    const int col = nt * 8 + t4 * 2;
                    float v0 = o[mt][nt][2*hh]     * s + smO[rl * OEP_LD + col]     * sp;
                    float v1 = o[mt][nt][2*hh + 1] * s + smO[rl * OEP_LD + col + 1] * sp;
                    float2 xi = *(const float2*)(xb + (size_t)rg * CDIM + col);
                    float2 res;
                    res.x = fmaf(gm, v0 * inv, xi.x);
                    res.y = fmaf(gm, v1 * inv, xi.y);
                    *(float2*)(out + ((size_t)b * NTOK + rg) * CDIM + col) = res;
                }
            }
        }
    }
}

extern "C" void kernel_launch(void* const* d_in, const int* in_sizes, int n_in,
                              void* d_out, int out_size)
{
    const float* x     = (const float*)d_in[0];
    const float* gamma = (const float*)d_in[1];
    float* out = (float*)d_out;

    cudaFuncSetAttribute(attn_mma_pv1_kernel,
                         cudaFuncAttributeMaxDynamicSharedMemorySize, SMEM_DYN);

    dim3 grid(NTOK / BM, BATCH);   // (36, 4) = 144 CTAs ~ one wave
    attn_mma_pv1_kernel<<<grid, 256, SMEM_DYN>>>(x, gamma, out);
}